// round 1
// baseline (speedup 1.0000x reference)
#include <cuda_runtime.h>

#define Nn 100000
#define Ee 1000000
#define NB ((size_t)Nn * 64 * sizeof(float))

// Scratch (device globals — no runtime allocation allowed)
__device__ float g_X[2][(size_t)Nn * 64];
__device__ float g_Y[2][(size_t)Nn * 64];
__device__ float g_A[2][(size_t)Nn * 64];
__device__ float g_D[2][Nn];

// ---------------------------------------------------------------------------
// Degree: deg[dst] += 1 per edge; then dinv = rsqrt(deg + 1)  (self-loop)
// ---------------------------------------------------------------------------
__global__ void deg_count_k(const int* __restrict__ f, const int* __restrict__ s,
                            float* __restrict__ d0, float* __restrict__ d1) {
    int e = blockIdx.x * blockDim.x + threadIdx.x;
    if (e < Ee) {
        atomicAdd(d0 + __ldg(f + Ee + e), 1.f);
        atomicAdd(d1 + __ldg(s + Ee + e), 1.f);
    }
}

__global__ void dinv_k(float* __restrict__ d0, float* __restrict__ d1) {
    int i = blockIdx.x * blockDim.x + threadIdx.x;
    if (i < Nn) {
        d0[i] = rsqrtf(d0[i] + 1.f);
        d1[i] = rsqrtf(d1[i] + 1.f);
    }
}

// ---------------------------------------------------------------------------
// Encoder hidden: out[r,j] = relu(b1[j] + sum_{k<4} x[r,k] * w1[k,j])
// ---------------------------------------------------------------------------
__global__ void enc_hidden_k(const float* __restrict__ x, const float* __restrict__ w1,
                             const float* __restrict__ b1, float* __restrict__ out) {
    int t = blockIdx.x * blockDim.x + threadIdx.x;
    if (t >= Nn * 64) return;
    int r = t >> 6, j = t & 63;
    float4 xv = *(const float4*)(x + (size_t)r * 4);
    float h = __ldg(b1 + j)
            + xv.x * __ldg(w1 + j)       + xv.y * __ldg(w1 + 64 + j)
            + xv.z * __ldg(w1 + 128 + j) + xv.w * __ldg(w1 + 192 + j);
    out[t] = fmaxf(h, 0.f);
}

// ---------------------------------------------------------------------------
// Generic 64-col GEMM over a 64-row tile.
// Input modes:
//   gcnIn=0: v = inA[r,c]                               (raw)
//   gcnIn=1: v = relu(dinv[r]*(inAgg[r,c]+inA[r,c]) + inBias[c])  (fused GCN epilogue)
// Output: out[r,c] ?= accum + (acc + outBias[c]) * (outDinv ? dinv[r] : 1)
// ---------------------------------------------------------------------------
__global__ __launch_bounds__(256) void gemm64_k(
    const float* __restrict__ inA, const float* __restrict__ inAgg,
    const float* __restrict__ inDinv, const float* __restrict__ inBias,
    const float* __restrict__ W, const float* __restrict__ outBias,
    const float* __restrict__ outDinv, float* __restrict__ out,
    int gcnIn, int accum) {
    __shared__ float Xs[64 * 64];
    __shared__ float Ws[64 * 64];
    int tid = threadIdx.x;
    int row0 = blockIdx.x * 64;
    size_t base = (size_t)row0 * 64;

#pragma unroll
    for (int t = 0; t < 16; t++) Ws[tid + t * 256] = W[tid + t * 256];
#pragma unroll
    for (int t = 0; t < 16; t++) {
        int lin = tid + t * 256;
        int r = lin >> 6;
        float v = 0.f;
        if (row0 + r < Nn) {
            size_t idx = base + lin;
            if (!gcnIn) {
                v = inA[idx];
            } else {
                v = fmaxf(inDinv[row0 + r] * (inAgg[idx] + inA[idx]) + __ldg(inBias + (lin & 63)), 0.f);
            }
        }
        Xs[lin] = v;
    }
    __syncthreads();

    int cx = (tid & 15) * 4;
    int ry = (tid >> 4) * 4;
    float acc[4][4];
#pragma unroll
    for (int i = 0; i < 4; i++)
#pragma unroll
        for (int j = 0; j < 4; j++) acc[i][j] = 0.f;

#pragma unroll 16
    for (int k = 0; k < 64; k++) {
        float4 wv = *(const float4*)(Ws + k * 64 + cx);
#pragma unroll
        for (int i = 0; i < 4; i++) {
            float xv = Xs[(ry + i) * 64 + k];
            acc[i][0] += xv * wv.x;
            acc[i][1] += xv * wv.y;
            acc[i][2] += xv * wv.z;
            acc[i][3] += xv * wv.w;
        }
    }

    float4 obv = outBias ? *(const float4*)(outBias + cx) : make_float4(0.f, 0.f, 0.f, 0.f);
#pragma unroll
    for (int i = 0; i < 4; i++) {
        int r = row0 + ry + i;
        if (r < Nn) {
            float sc = outDinv ? outDinv[r] : 1.f;
            float4 o = make_float4((acc[i][0] + obv.x) * sc, (acc[i][1] + obv.y) * sc,
                                   (acc[i][2] + obv.z) * sc, (acc[i][3] + obv.w) * sc);
            float* p = out + (size_t)r * 64 + cx;
            if (accum) {
                float4 pv = *(const float4*)p;
                o.x += pv.x; o.y += pv.y; o.z += pv.z; o.w += pv.w;
            }
            *(float4*)p = o;
        }
    }
}

// ---------------------------------------------------------------------------
// Edge scatter: agg[dst, :] += y[src, :]   (16 threads/edge, float4 red ops)
// ---------------------------------------------------------------------------
__global__ __launch_bounds__(256) void scatter_k(const float* __restrict__ y,
                                                 const int* __restrict__ ei,
                                                 float* __restrict__ agg) {
    int t = blockIdx.x * blockDim.x + threadIdx.x;
    int e = t >> 4;
    if (e >= Ee) return;
    int j = (t & 15) * 4;
    int src = __ldg(ei + e);
    int dst = __ldg(ei + Ee + e);
    float4 v = *(const float4*)(y + (size_t)src * 64 + j);
    atomicAdd((float4*)(agg + (size_t)dst * 64 + j), v);
}

// ---------------------------------------------------------------------------
// Head: fused = relu(h1) @ fw2 + fb2; feats = fused@ow+ob; types = fused@cw+cb
// ---------------------------------------------------------------------------
__global__ __launch_bounds__(256) void head_k(
    const float* __restrict__ h1, const float* __restrict__ fw2, const float* __restrict__ fb2,
    const float* __restrict__ ow, const float* __restrict__ ob,
    const float* __restrict__ cw, const float* __restrict__ cb,
    float* __restrict__ outF, float* __restrict__ outT) {
    __shared__ float Xs[64 * 64];
    __shared__ float Ws[64 * 64];
    int tid = threadIdx.x;
    int row0 = blockIdx.x * 64;
    size_t base = (size_t)row0 * 64;

#pragma unroll
    for (int t = 0; t < 16; t++) Ws[tid + t * 256] = fw2[tid + t * 256];
#pragma unroll
    for (int t = 0; t < 16; t++) {
        int lin = tid + t * 256;
        int r = lin >> 6;
        Xs[lin] = (row0 + r < Nn) ? fmaxf(h1[base + lin], 0.f) : 0.f;
    }
    __syncthreads();

    int cx = (tid & 15) * 4;
    int ry = (tid >> 4) * 4;
    float acc[4][4];
#pragma unroll
    for (int i = 0; i < 4; i++)
#pragma unroll
        for (int j = 0; j < 4; j++) acc[i][j] = 0.f;

#pragma unroll 16
    for (int k = 0; k < 64; k++) {
        float4 wv = *(const float4*)(Ws + k * 64 + cx);
#pragma unroll
        for (int i = 0; i < 4; i++) {
            float xv = Xs[(ry + i) * 64 + k];
            acc[i][0] += xv * wv.x;
            acc[i][1] += xv * wv.y;
            acc[i][2] += xv * wv.z;
            acc[i][3] += xv * wv.w;
        }
    }
    __syncthreads();  // everyone done reading Xs/Ws

    float4 bb = *(const float4*)(fb2 + cx);
#pragma unroll
    for (int i = 0; i < 4; i++) {
        Xs[(ry + i) * 64 + cx + 0] = acc[i][0] + bb.x;
        Xs[(ry + i) * 64 + cx + 1] = acc[i][1] + bb.y;
        Xs[(ry + i) * 64 + cx + 2] = acc[i][2] + bb.z;
        Xs[(ry + i) * 64 + cx + 3] = acc[i][3] + bb.w;
    }
#pragma unroll
    for (int t = 0; t < 8; t++) Ws[tid + t * 256] = ow[tid + t * 256];  // 64x32
    if (tid < 128) Ws[2048 + tid] = cw[tid];                             // 64x2
    __syncthreads();

    // node_features: 64 rows x 32 cols, 8 rows per thread
    int c = tid & 31;
    int rb = (tid >> 5) * 8;
    for (int rr = 0; rr < 8; rr++) {
        int r = rb + rr;
        float a = __ldg(ob + c);
#pragma unroll 16
        for (int k = 0; k < 64; k++) a += Xs[r * 64 + k] * Ws[k * 32 + c];
        if (row0 + r < Nn) outF[(size_t)(row0 + r) * 32 + c] = a;
    }
    // node_types: 64 rows x 2 cols
    if (tid < 128) {
        int r = tid >> 1, cc = tid & 1;
        float a = __ldg(cb + cc);
#pragma unroll 16
        for (int k = 0; k < 64; k++) a += Xs[r * 64 + k] * Ws[2048 + k * 2 + cc];
        if (row0 + r < Nn) outT[(size_t)(row0 + r) * 2 + cc] = a;
    }
}

// ---------------------------------------------------------------------------
extern "C" void kernel_launch(void* const* d_in, const int* in_sizes, int n_in,
                              void* d_out, int out_size) {
    const float* xin[2] = {(const float*)d_in[0], (const float*)d_in[1]};
    const int* ei[2]    = {(const int*)d_in[2], (const int*)d_in[3]};
    const float* ew1[2] = {(const float*)d_in[4],  (const float*)d_in[10]};
    const float* eb1[2] = {(const float*)d_in[5],  (const float*)d_in[11]};
    const float* ew2[2] = {(const float*)d_in[6],  (const float*)d_in[12]};
    const float* eb2[2] = {(const float*)d_in[7],  (const float*)d_in[13]};
    const float* cw[2]  = {(const float*)d_in[8],  (const float*)d_in[14]};
    const float* cb[2]  = {(const float*)d_in[9],  (const float*)d_in[15]};
    const float* fw1 = (const float*)d_in[16];
    const float* fb1 = (const float*)d_in[17];
    const float* fw2 = (const float*)d_in[18];
    const float* fb2 = (const float*)d_in[19];
    const float* ow  = (const float*)d_in[20];
    const float* obv = (const float*)d_in[21];
    const float* clw = (const float*)d_in[22];
    const float* clb = (const float*)d_in[23];

    float *Xb, *Yb, *Ab, *Db;
    cudaGetSymbolAddress((void**)&Xb, g_X);
    cudaGetSymbolAddress((void**)&Yb, g_Y);
    cudaGetSymbolAddress((void**)&Ab, g_A);
    cudaGetSymbolAddress((void**)&Db, g_D);
    float* Xg[2] = {Xb, Xb + (size_t)Nn * 64};
    float* Yg[2] = {Yb, Yb + (size_t)Nn * 64};
    float* Ag[2] = {Ab, Ab + (size_t)Nn * 64};
    float* Dg[2] = {Db, Db + Nn};

    // Degrees -> dinv (both graphs in one pass)
    cudaMemsetAsync(Dg[0], 0, Nn * sizeof(float));
    cudaMemsetAsync(Dg[1], 0, Nn * sizeof(float));
    deg_count_k<<<(Ee + 255) / 256, 256>>>(ei[0], ei[1], Dg[0], Dg[1]);
    dinv_k<<<(Nn + 255) / 256, 256>>>(Dg[0], Dg[1]);

    const int GB = (Nn + 63) / 64;       // 1563 row tiles
    const int SG = (Ee * 16) / 256;      // scatter grid (exact)

    for (int g = 0; g < 2; g++) {
        // encoder MLP2: hidden = relu(x@w1+b1) -> Y ; X = hidden@w2+b2
        enc_hidden_k<<<(Nn * 64 + 255) / 256, 256>>>(xin[g], ew1[g], eb1[g], Yg[g]);
        gemm64_k<<<GB, 256>>>(Yg[g], nullptr, nullptr, nullptr, ew2[g], eb2[g], nullptr, Xg[g], 0, 0);

        // GCN layer 0: y = (X @ W0) * dinv ; agg = scatter(y)
        gemm64_k<<<GB, 256>>>(Xg[g], nullptr, nullptr, nullptr, cw[g], nullptr, Dg[g], Yg[g], 0, 0);
        cudaMemsetAsync(Ag[g], 0, NB);
        scatter_k<<<SG, 256>>>(Yg[g], ei[g], Ag[g]);

        // GCN layer 1: x1 = relu(dinv*(agg+y)+b0) fused into GEMM input
        gemm64_k<<<GB, 256>>>(Yg[g], Ag[g], Dg[g], cb[g], cw[g] + 4096, nullptr, Dg[g], Xg[g], 1, 0);
        cudaMemsetAsync(Ag[g], 0, NB);
        scatter_k<<<SG, 256>>>(Xg[g], ei[g], Ag[g]);

        // GCN layer 2
        gemm64_k<<<GB, 256>>>(Xg[g], Ag[g], Dg[g], cb[g] + 64, cw[g] + 8192, nullptr, Dg[g], Yg[g], 1, 0);
        cudaMemsetAsync(Ag[g], 0, NB);
        scatter_k<<<SG, 256>>>(Yg[g], ei[g], Ag[g]);
    }

    // Fusion layer 1 (K=128 via two accumulating K=64 passes); h1 -> Xg[0]
    gemm64_k<<<GB, 256>>>(Yg[0], Ag[0], Dg[0], cb[0] + 128, fw1, fb1, nullptr, Xg[0], 1, 0);
    gemm64_k<<<GB, 256>>>(Yg[1], Ag[1], Dg[1], cb[1] + 128, fw1 + 4096, nullptr, nullptr, Xg[0], 1, 1);

    // Fusion layer 2 + both output heads
    head_k<<<GB, 256>>>(Xg[0], fw2, fb2, ow, obv, clw, clb,
                        (float*)d_out, (float*)d_out + (size_t)Nn * 32);
}

// round 2
// speedup vs baseline: 1.0842x; 1.0842x over previous
#include <cuda_runtime.h>

#define Nn 100000
#define Ee 1000000
#define NB ((size_t)Nn * 64 * sizeof(float))

// Scratch (device globals — no runtime allocation allowed)
__device__ float g_X[2][(size_t)Nn * 64];
__device__ float g_Y[2][(size_t)Nn * 64];
__device__ float g_A[2][(size_t)Nn * 64];
__device__ float g_D[2][Nn];

// ---------------------------------------------------------------------------
// Degree: deg[dst] += 1 per edge; then dinv = rsqrt(deg + 1)  (self-loop)
// ---------------------------------------------------------------------------
__global__ void deg_count_k(const int* __restrict__ f, const int* __restrict__ s,
                            float* __restrict__ d0, float* __restrict__ d1) {
    int e = blockIdx.x * blockDim.x + threadIdx.x;
    if (e < Ee) {
        atomicAdd(d0 + __ldg(f + Ee + e), 1.f);
        atomicAdd(d1 + __ldg(s + Ee + e), 1.f);
    }
}

__global__ void dinv_k(float* __restrict__ d0, float* __restrict__ d1) {
    int i = blockIdx.x * blockDim.x + threadIdx.x;
    if (i < Nn) {
        d0[i] = rsqrtf(d0[i] + 1.f);
        d1[i] = rsqrtf(d1[i] + 1.f);
    }
}

// ---------------------------------------------------------------------------
// Encoder hidden: out[r,j] = relu(b1[j] + sum_{k<4} x[r,k] * w1[k,j])
// ---------------------------------------------------------------------------
__global__ void enc_hidden_k(const float* __restrict__ x, const float* __restrict__ w1,
                             const float* __restrict__ b1, float* __restrict__ out) {
    int t = blockIdx.x * blockDim.x + threadIdx.x;
    if (t >= Nn * 64) return;
    int r = t >> 6, j = t & 63;
    float4 xv = *(const float4*)(x + (size_t)r * 4);
    float h = __ldg(b1 + j)
            + xv.x * __ldg(w1 + j)       + xv.y * __ldg(w1 + 64 + j)
            + xv.z * __ldg(w1 + 128 + j) + xv.w * __ldg(w1 + 192 + j);
    out[t] = fmaxf(h, 0.f);
}

// ---------------------------------------------------------------------------
// 128-row x 64-col GEMM tile, 256 threads, 8x4 register blocking, all-float4 LDS.
// Input modes:
//   gcnIn=0: v = inA[r,c]
//   gcnIn=1: v = relu(dinv[r]*(inAgg[r,c]+inA[r,c]) + inBias[c])  (fused GCN epilogue)
// Output: out[r,c] (+= if accum) (acc + outBias[c]) * (outDinv ? dinv[r] : 1)
// ---------------------------------------------------------------------------
__global__ __launch_bounds__(256) void gemm128_k(
    const float* __restrict__ inA, const float* __restrict__ inAgg,
    const float* __restrict__ inDinv, const float* __restrict__ inBias,
    const float* __restrict__ W, const float* __restrict__ outBias,
    const float* __restrict__ outDinv, float* __restrict__ out,
    int gcnIn, int accum) {
    __shared__ float Xs[128 * 64];   // 32 KB
    __shared__ float Ws[64 * 64];    // 16 KB

    int tid = threadIdx.x;
    int row0 = blockIdx.x * 128;

    // Load W (4096 floats = 1024 float4)
    const float4* W4 = (const float4*)W;
#pragma unroll
    for (int t = 0; t < 4; t++) ((float4*)Ws)[tid + t * 256] = __ldg(W4 + tid + t * 256);

    // Load X tile (2048 float4), with optional fused GCN epilogue
#pragma unroll
    for (int t = 0; t < 8; t++) {
        int lin = tid + t * 256;        // float4 index; row = lin>>4, col4 = lin&15
        int r = lin >> 4;
        float4 v = make_float4(0.f, 0.f, 0.f, 0.f);
        if (row0 + r < Nn) {
            size_t idx = (size_t)(row0 + r) * 16 + (lin & 15);
            if (!gcnIn) {
                v = ((const float4*)inA)[idx];
            } else {
                float4 a = ((const float4*)inA)[idx];
                float4 g = ((const float4*)inAgg)[idx];
                float dv = inDinv[row0 + r];
                float4 b = __ldg((const float4*)inBias + (lin & 15));
                v.x = fmaxf(fmaf(dv, g.x + a.x, b.x), 0.f);
                v.y = fmaxf(fmaf(dv, g.y + a.y, b.y), 0.f);
                v.z = fmaxf(fmaf(dv, g.z + a.z, b.z), 0.f);
                v.w = fmaxf(fmaf(dv, g.w + a.w, b.w), 0.f);
            }
        }
        ((float4*)Xs)[lin] = v;
    }
    __syncthreads();

    int cx = (tid & 15) * 4;   // output column base
    int ry = (tid >> 4) * 8;   // output row base (8 rows per thread)
    float acc[8][4];
#pragma unroll
    for (int i = 0; i < 8; i++)
#pragma unroll
        for (int j = 0; j < 4; j++) acc[i][j] = 0.f;

#pragma unroll
    for (int k0 = 0; k0 < 64; k0 += 4) {
        float4 w0 = *(const float4*)(Ws + (k0 + 0) * 64 + cx);
        float4 w1 = *(const float4*)(Ws + (k0 + 1) * 64 + cx);
        float4 w2 = *(const float4*)(Ws + (k0 + 2) * 64 + cx);
        float4 w3 = *(const float4*)(Ws + (k0 + 3) * 64 + cx);
#pragma unroll
        for (int i = 0; i < 8; i++) {
            float4 a = *(const float4*)(Xs + (ry + i) * 64 + k0);
            acc[i][0] = fmaf(a.x, w0.x, fmaf(a.y, w1.x, fmaf(a.z, w2.x, fmaf(a.w, w3.x, acc[i][0]))));
            acc[i][1] = fmaf(a.x, w0.y, fmaf(a.y, w1.y, fmaf(a.z, w2.y, fmaf(a.w, w3.y, acc[i][1]))));
            acc[i][2] = fmaf(a.x, w0.z, fmaf(a.y, w1.z, fmaf(a.z, w2.z, fmaf(a.w, w3.z, acc[i][2]))));
            acc[i][3] = fmaf(a.x, w0.w, fmaf(a.y, w1.w, fmaf(a.z, w2.w, fmaf(a.w, w3.w, acc[i][3]))));
        }
    }

    float4 obv = outBias ? __ldg((const float4*)(outBias + cx))
                         : make_float4(0.f, 0.f, 0.f, 0.f);
#pragma unroll
    for (int i = 0; i < 8; i++) {
        int r = row0 + ry + i;
        if (r < Nn) {
            float sc = outDinv ? outDinv[r] : 1.f;
            float4 o = make_float4((acc[i][0] + obv.x) * sc, (acc[i][1] + obv.y) * sc,
                                   (acc[i][2] + obv.z) * sc, (acc[i][3] + obv.w) * sc);
            float* p = out + (size_t)r * 64 + cx;
            if (accum) {
                float4 pv = *(const float4*)p;
                o.x += pv.x; o.y += pv.y; o.z += pv.z; o.w += pv.w;
            }
            *(float4*)p = o;
        }
    }
}

// ---------------------------------------------------------------------------
// Edge scatter: agg[dst, :] += y[src, :]   (16 threads/edge, float4 red ops)
// ---------------------------------------------------------------------------
__global__ __launch_bounds__(256) void scatter_k(const float* __restrict__ y,
                                                 const int* __restrict__ ei,
                                                 float* __restrict__ agg) {
    int t = blockIdx.x * blockDim.x + threadIdx.x;
    int e = t >> 4;
    if (e >= Ee) return;
    int j = (t & 15) * 4;
    int src = __ldg(ei + e);
    int dst = __ldg(ei + Ee + e);
    float4 v = *(const float4*)(y + (size_t)src * 64 + j);
    atomicAdd((float4*)(agg + (size_t)dst * 64 + j), v);
}

// ---------------------------------------------------------------------------
// Head: fused = relu(h1) @ fw2 + fb2; feats = fused@ow+ob; types = fused@cw+cb
// ---------------------------------------------------------------------------
__global__ __launch_bounds__(256) void head_k(
    const float* __restrict__ h1, const float* __restrict__ fw2, const float* __restrict__ fb2,
    const float* __restrict__ ow, const float* __restrict__ ob,
    const float* __restrict__ cw, const float* __restrict__ cb,
    float* __restrict__ outF, float* __restrict__ outT) {
    __shared__ float Xs[64 * 64];
    __shared__ float Ws[64 * 64];
    int tid = threadIdx.x;
    int row0 = blockIdx.x * 64;
    size_t base = (size_t)row0 * 64;

#pragma unroll
    for (int t = 0; t < 16; t++) Ws[tid + t * 256] = fw2[tid + t * 256];
#pragma unroll
    for (int t = 0; t < 16; t++) {
        int lin = tid + t * 256;
        int r = lin >> 6;
        Xs[lin] = (row0 + r < Nn) ? fmaxf(h1[base + lin], 0.f) : 0.f;
    }
    __syncthreads();

    int cx = (tid & 15) * 4;
    int ry = (tid >> 4) * 4;
    float acc[4][4];
#pragma unroll
    for (int i = 0; i < 4; i++)
#pragma unroll
        for (int j = 0; j < 4; j++) acc[i][j] = 0.f;

#pragma unroll
    for (int k0 = 0; k0 < 64; k0 += 4) {
        float4 w0 = *(const float4*)(Ws + (k0 + 0) * 64 + cx);
        float4 w1 = *(const float4*)(Ws + (k0 + 1) * 64 + cx);
        float4 w2 = *(const float4*)(Ws + (k0 + 2) * 64 + cx);
        float4 w3 = *(const float4*)(Ws + (k0 + 3) * 64 + cx);
#pragma unroll
        for (int i = 0; i < 4; i++) {
            float4 a = *(const float4*)(Xs + (ry + i) * 64 + k0);
            acc[i][0] = fmaf(a.x, w0.x, fmaf(a.y, w1.x, fmaf(a.z, w2.x, fmaf(a.w, w3.x, acc[i][0]))));
            acc[i][1] = fmaf(a.x, w0.y, fmaf(a.y, w1.y, fmaf(a.z, w2.y, fmaf(a.w, w3.y, acc[i][1]))));
            acc[i][2] = fmaf(a.x, w0.z, fmaf(a.y, w1.z, fmaf(a.z, w2.z, fmaf(a.w, w3.z, acc[i][2]))));
            acc[i][3] = fmaf(a.x, w0.w, fmaf(a.y, w1.w, fmaf(a.z, w2.w, fmaf(a.w, w3.w, acc[i][3]))));
        }
    }
    __syncthreads();  // everyone done reading Xs/Ws

    float4 bb = *(const float4*)(fb2 + cx);
#pragma unroll
    for (int i = 0; i < 4; i++) {
        Xs[(ry + i) * 64 + cx + 0] = acc[i][0] + bb.x;
        Xs[(ry + i) * 64 + cx + 1] = acc[i][1] + bb.y;
        Xs[(ry + i) * 64 + cx + 2] = acc[i][2] + bb.z;
        Xs[(ry + i) * 64 + cx + 3] = acc[i][3] + bb.w;
    }
#pragma unroll
    for (int t = 0; t < 8; t++) Ws[tid + t * 256] = ow[tid + t * 256];  // 64x32
    if (tid < 128) Ws[2048 + tid] = cw[tid];                             // 64x2
    __syncthreads();

    // node_features: 64 rows x 32 cols, 8 rows per thread
    int c = tid & 31;
    int rb = (tid >> 5) * 8;
    for (int rr = 0; rr < 8; rr++) {
        int r = rb + rr;
        float a = __ldg(ob + c);
#pragma unroll 16
        for (int k = 0; k < 64; k++) a += Xs[r * 64 + k] * Ws[k * 32 + c];
        if (row0 + r < Nn) outF[(size_t)(row0 + r) * 32 + c] = a;
    }
    // node_types: 64 rows x 2 cols
    if (tid < 128) {
        int r = tid >> 1, cc = tid & 1;
        float a = __ldg(cb + cc);
#pragma unroll 16
        for (int k = 0; k < 64; k++) a += Xs[r * 64 + k] * Ws[2048 + k * 2 + cc];
        if (row0 + r < Nn) outT[(size_t)(row0 + r) * 2 + cc] = a;
    }
}

// ---------------------------------------------------------------------------
extern "C" void kernel_launch(void* const* d_in, const int* in_sizes, int n_in,
                              void* d_out, int out_size) {
    const float* xin[2] = {(const float*)d_in[0], (const float*)d_in[1]};
    const int* ei[2]    = {(const int*)d_in[2], (const int*)d_in[3]};
    const float* ew1[2] = {(const float*)d_in[4],  (const float*)d_in[10]};
    const float* eb1[2] = {(const float*)d_in[5],  (const float*)d_in[11]};
    const float* ew2[2] = {(const float*)d_in[6],  (const float*)d_in[12]};
    const float* eb2[2] = {(const float*)d_in[7],  (const float*)d_in[13]};
    const float* cw[2]  = {(const float*)d_in[8],  (const float*)d_in[14]};
    const float* cb[2]  = {(const float*)d_in[9],  (const float*)d_in[15]};
    const float* fw1 = (const float*)d_in[16];
    const float* fb1 = (const float*)d_in[17];
    const float* fw2 = (const float*)d_in[18];
    const float* fb2 = (const float*)d_in[19];
    const float* ow  = (const float*)d_in[20];
    const float* obv = (const float*)d_in[21];
    const float* clw = (const float*)d_in[22];
    const float* clb = (const float*)d_in[23];

    float *Xb, *Yb, *Ab, *Db;
    cudaGetSymbolAddress((void**)&Xb, g_X);
    cudaGetSymbolAddress((void**)&Yb, g_Y);
    cudaGetSymbolAddress((void**)&Ab, g_A);
    cudaGetSymbolAddress((void**)&Db, g_D);
    float* Xg[2] = {Xb, Xb + (size_t)Nn * 64};
    float* Yg[2] = {Yb, Yb + (size_t)Nn * 64};
    float* Ag[2] = {Ab, Ab + (size_t)Nn * 64};
    float* Dg[2] = {Db, Db + Nn};

    // Degrees -> dinv (both graphs in one pass)
    cudaMemsetAsync(Dg[0], 0, Nn * sizeof(float));
    cudaMemsetAsync(Dg[1], 0, Nn * sizeof(float));
    deg_count_k<<<(Ee + 255) / 256, 256>>>(ei[0], ei[1], Dg[0], Dg[1]);
    dinv_k<<<(Nn + 255) / 256, 256>>>(Dg[0], Dg[1]);

    const int GB  = (Nn + 63) / 64;      // 64-row tiles (head kernel)
    const int GB2 = (Nn + 127) / 128;    // 128-row tiles (gemm128)
    const int SG  = (Ee * 16) / 256;     // scatter grid (exact)

    for (int g = 0; g < 2; g++) {
        // encoder MLP2: hidden = relu(x@w1+b1) -> Y ; X = hidden@w2+b2
        enc_hidden_k<<<(Nn * 64 + 255) / 256, 256>>>(xin[g], ew1[g], eb1[g], Yg[g]);
        gemm128_k<<<GB2, 256>>>(Yg[g], nullptr, nullptr, nullptr, ew2[g], eb2[g], nullptr, Xg[g], 0, 0);

        // GCN layer 0: y = (X @ W0) * dinv ; agg = scatter(y)
        gemm128_k<<<GB2, 256>>>(Xg[g], nullptr, nullptr, nullptr, cw[g], nullptr, Dg[g], Yg[g], 0, 0);
        cudaMemsetAsync(Ag[g], 0, NB);
        scatter_k<<<SG, 256>>>(Yg[g], ei[g], Ag[g]);

        // GCN layer 1: x1 = relu(dinv*(agg+y)+b0) fused into GEMM input
        gemm128_k<<<GB2, 256>>>(Yg[g], Ag[g], Dg[g], cb[g], cw[g] + 4096, nullptr, Dg[g], Xg[g], 1, 0);
        cudaMemsetAsync(Ag[g], 0, NB);
        scatter_k<<<SG, 256>>>(Xg[g], ei[g], Ag[g]);

        // GCN layer 2
        gemm128_k<<<GB2, 256>>>(Xg[g], Ag[g], Dg[g], cb[g] + 64, cw[g] + 8192, nullptr, Dg[g], Yg[g], 1, 0);
        cudaMemsetAsync(Ag[g], 0, NB);
        scatter_k<<<SG, 256>>>(Yg[g], ei[g], Ag[g]);
    }

    // Fusion layer 1 (K=128 via two accumulating K=64 passes); h1 -> Xg[0]
    gemm128_k<<<GB2, 256>>>(Yg[0], Ag[0], Dg[0], cb[0] + 128, fw1, fb1, nullptr, Xg[0], 1, 0);
    gemm128_k<<<GB2, 256>>>(Yg[1], Ag[1], Dg[1], cb[1] + 128, fw1 + 4096, nullptr, nullptr, Xg[0], 1, 1);

    // Fusion layer 2 + both output heads
    head_k<<<GB, 256>>>(Xg[0], fw2, fb2, ow, obv, clw, clb,
                        (float*)d_out, (float*)d_out + (size_t)Nn * 32);
}